// round 10
// baseline (speedup 1.0000x reference)
#include <cuda_runtime.h>

#define N 2048
#define K 16
#define BATCH 16384
#define RPB 16
#define THREADS 512
#define GRID_MAIN 152
#define NTILES (BATCH / RPB)
#define STAGES 8
#define INFLIGHT 6       // wait_group 6 -> 7 groups (3.5 KB) in flight per warp
#define CROWS 14         // compose rows per CTA: 152*14 = 2128 >= 2048

// Final composed weights, layout [t][m4][rho][4]:
//   g_Wfin[((t*4 + (m>>2))*128 + rho)*4 + (m&3)]
__device__ float g_Wfin[K * K * 128];
// Monotonic device-wide barrier counter (never reset; target derived per phase)
__device__ unsigned g_bar;

// ---------------------------------------------------------------------------
// Packed f32x2 + cp.async helpers
// ---------------------------------------------------------------------------
__device__ __forceinline__ unsigned long long fma2(unsigned long long a,
                                                   unsigned long long b,
                                                   unsigned long long c) {
    unsigned long long d;
    asm("fma.rn.f32x2 %0, %1, %2, %3;" : "=l"(d) : "l"(a), "l"(b), "l"(c));
    return d;
}
__device__ __forceinline__ unsigned long long dup2(float v) {
    unsigned long long r;
    asm("mov.b64 %0, {%1, %1};" : "=l"(r) : "f"(v));
    return r;
}
__device__ __forceinline__ void unpack2(unsigned long long v, float& lo, float& hi) {
    asm("mov.b64 {%0, %1}, %2;" : "=f"(lo), "=f"(hi) : "l"(v));
}
__device__ __forceinline__ void cp_async16(unsigned smem_addr, const void* gptr) {
    asm volatile("cp.async.cg.shared.global [%0], [%1], 16;"
                 :: "r"(smem_addr), "l"(gptr) : "memory");
}
__device__ __forceinline__ void cp_commit() {
    asm volatile("cp.async.commit_group;" ::: "memory");
}
__device__ __forceinline__ void cp_wait() {
    asm volatile("cp.async.wait_group %0;" :: "n"(INFLIGHT) : "memory");
}
__device__ __forceinline__ unsigned ld_bar() {
    unsigned v;
    asm volatile("ld.global.cg.u32 %0, [%1];" : "=r"(v) : "l"(&g_bar));
    return v;
}

// ---------------------------------------------------------------------------
// Single persistent kernel:
//   Phase A (all 152 CTAs): compose a 14-row slice of
//     Wfin = scaling * (W0 @ W1 @ W2)  ->  g_Wfin   (~0.5 us across the chip)
//     pattern: c = (r + 128*s + 3) % N;  r = rho + 128*t, m = (t+s)&15
//   Device-wide barrier (monotonic counter; all CTAs co-resident at 1/SM)
//     - the x cp.async ring prologue is issued BEFORE the spin, so DRAM
//       prefetch overlaps barrier latency.
//   Phase B: y = relu(x @ Wfin + bias), identical to the validated R6 loop:
//     16 warp-private 8-stage cp.async rings (no block barriers), W resident
//     in smem ([t][m4][rho][4] -> float4 IS two fma2 operands), __stcs
//     epilogue (warp-contiguous 128 B runs).
// ---------------------------------------------------------------------------
#define SM_W      0
#define SM_X      (32 * 1024)                       // floats
#define SM_BIAS   (SM_X + 16 * STAGES * 128)        // + 16384 = 49152
#define SM_FLOATS (SM_BIAS + N)                     // 51200 floats = 200 KB

__global__ void __launch_bounds__(THREADS, 1)
k_main(const float* __restrict__ x, const float* __restrict__ bias,
       float* __restrict__ y,
       const float* __restrict__ v0, const float* __restrict__ v1,
       const float* __restrict__ v2, const float* __restrict__ scaling) {
    extern __shared__ float smem[];

    const int tid  = threadIdx.x;
    const int lane = tid & 31;
    const int warp = tid >> 5;
    const int grp  = warp >> 2;                 // 0..3 -> rows grp*4..grp*4+3
    const int wsub = warp & 3;                  // 32-rho window
    const int rho  = wsub * 32 + lane;
    const int crow = lane >> 3;                 // row this lane copies (0..3)
    const int coff = (lane & 7) * 4;            // float offset in 32-float window

    // ---------------- Phase A: compose this CTA's Wfin slice ----------------
    // w01 staged in the (not yet used) W smem area, stride 17 vs conflicts.
    {
        float* w01 = smem + SM_W;
        const int s  = tid & 15;
        const int rl = tid >> 4;                // 0..31; only rl<CROWS works
        const int r  = blockIdx.x * CROWS + rl;
        if (rl < CROWS && r < N) {
            float acc = 0.f;
#pragma unroll
            for (int k0 = 0; k0 < K; k0++) {
                int arow = (r + 128 * k0) & (N - 1);
                acc = fmaf(v0[r * K + k0], v1[arow * K + ((s - k0) & (K - 1))], acc);
            }
            w01[rl * 17 + s] = acc;
        }
        __syncthreads();
        if (rl < CROWS && r < N) {
            float sc = scaling[0];
            float acc2 = 0.f;
#pragma unroll
            for (int s01 = 0; s01 < K; s01++) {
                int brow = (r + 128 * s01 + 1) & (N - 1);
                acc2 = fmaf(w01[rl * 17 + s01], v2[brow * K + ((s - s01) & (K - 1))], acc2);
            }
            int rr = r & 127;
            int t  = r >> 7;
            int m  = (t + s) & (K - 1);
            g_Wfin[((t * 4 + (m >> 2)) * 128 + rr) * 4 + (m & 3)] = sc * acc2;
        }
        __threadfence();
        __syncthreads();
    }

    // Arrive at the device-wide barrier
    __shared__ unsigned s_target;
    if (tid == 0) {
        unsigned old = atomicAdd(&g_bar, 1u);
        s_target = (old / GRID_MAIN + 1u) * GRID_MAIN;
    }

    // ------- x-ring prologue: overlap DRAM prefetch with the barrier -------
    float* ring = smem + SM_X + warp * (STAGES * 128);
    const unsigned ring_sa = (unsigned)__cvta_generic_to_shared(ring)
                           + (unsigned)(crow * 32 + coff) * 4;
    const size_t lane_off = (size_t)(grp * 4 + crow) * N + wsub * 32 + coff;
    const size_t tile_step = (size_t)GRID_MAIN * RPB * N;

    int tile = blockIdx.x;
    const float* cur = x + (size_t)tile * RPB * N + lane_off;
#pragma unroll
    for (int s = 0; s < STAGES - 1; s++) {
        cp_async16(ring_sa + (unsigned)(s * 512), cur + s * 128);
        cp_commit();
    }

    // Spin (tid 0 only), then release the block
    __syncthreads();                   // s_target visible to nobody needed but order
    if (tid == 0) {
        const unsigned tgt = s_target;
        while (ld_bar() < tgt) { }
        __threadfence();               // acquire: order g_Wfin reads after counter
    }
    __syncthreads();

    // Load resident W (float4) + bias  (g_Wfin now complete; L1 cold this launch)
    {
        const float4* src = (const float4*)g_Wfin;
        float4* dst = (float4*)(smem + SM_W);
#pragma unroll
        for (int i = tid; i < (K * K * 128) / 4; i += THREADS) dst[i] = src[i];
        for (int i = tid; i < N; i += THREADS) smem[SM_BIAS + i] = bias[i];
    }
    __syncthreads();

    // --------------------------- Phase B: main loop --------------------------
    for (; tile < NTILES; tile += GRID_MAIN) {
        const bool has_next = (tile + GRID_MAIN) < NTILES;
        const float* nxt = has_next ? cur + tile_step : cur;  // clamp: dummy re-read

        unsigned long long acc[4][8];
#pragma unroll
        for (int j = 0; j < 4; j++)
#pragma unroll
            for (int p = 0; p < 8; p++) acc[j][p] = 0ull;

#pragma unroll
        for (int t = 0; t < 16; t++) {
            cp_wait();
            __syncwarp();

            const float* xs = ring + (t & (STAGES - 1)) * 128;
            unsigned long long px0 = dup2(xs[lane]);
            unsigned long long px1 = dup2(xs[32 + lane]);
            unsigned long long px2 = dup2(xs[64 + lane]);
            unsigned long long px3 = dup2(xs[96 + lane]);

            // Refill: global stage t+7 (rolls into next tile at the tail)
            {
                const int s7 = t + (STAGES - 1);
                const float* src = (s7 < 16) ? (cur + s7 * 128)
                                             : (nxt + (s7 - 16) * 128);
                cp_async16(ring_sa + (unsigned)((s7 & (STAGES - 1)) * 512), src);
                cp_commit();
            }

            const float* wrow = smem + SM_W + t * 2048 + rho * 4;
#pragma unroll
            for (int m4 = 0; m4 < 4; m4++) {
                // float4 = two f32x2 operands for (m, m+1): no repacking
                ulonglong2 w = *(const ulonglong2*)(wrow + m4 * 512);
                acc[0][2 * m4]     = fma2(px0, w.x, acc[0][2 * m4]);
                acc[1][2 * m4]     = fma2(px1, w.x, acc[1][2 * m4]);
                acc[2][2 * m4]     = fma2(px2, w.x, acc[2][2 * m4]);
                acc[3][2 * m4]     = fma2(px3, w.x, acc[3][2 * m4]);
                acc[0][2 * m4 + 1] = fma2(px0, w.y, acc[0][2 * m4 + 1]);
                acc[1][2 * m4 + 1] = fma2(px1, w.y, acc[1][2 * m4 + 1]);
                acc[2][2 * m4 + 1] = fma2(px2, w.y, acc[2][2 * m4 + 1]);
                acc[3][2 * m4 + 1] = fma2(px3, w.y, acc[3][2 * m4 + 1]);
            }
        }
        cur = nxt;

        // Epilogue: bias + relu + streaming stores (warp-contiguous 128 B runs)
        float* yr = y + ((size_t)tile * RPB + grp * 4) * N;
#pragma unroll
        for (int p = 0; p < 8; p++) {
            const int c0 = (rho + 3 + 256 * p) & (N - 1);
            const int c1 = (c0 + 128) & (N - 1);
            const float b0 = smem[SM_BIAS + c0];
            const float b1 = smem[SM_BIAS + c1];
#pragma unroll
            for (int j = 0; j < 4; j++) {
                float lo, hi;
                unpack2(acc[j][p], lo, hi);
                __stcs(yr + (size_t)j * N + c0, fmaxf(lo + b0, 0.f));
                __stcs(yr + (size_t)j * N + c1, fmaxf(hi + b1, 0.f));
            }
        }
    }
}

// ---------------------------------------------------------------------------
// Launch: ONE kernel, one graph node. Inputs: x, vals0, vals1, vals2, rows0,
// cols0, rows1, cols1, rows2, cols2, scaling, bias
// ---------------------------------------------------------------------------
extern "C" void kernel_launch(void* const* d_in, const int* in_sizes, int n_in,
                              void* d_out, int out_size) {
    const float* x       = (const float*)d_in[0];
    const float* v0      = (const float*)d_in[1];
    const float* v1      = (const float*)d_in[2];
    const float* v2      = (const float*)d_in[3];
    const float* scaling = (const float*)d_in[10];
    const float* bias    = (const float*)d_in[11];
    float* y = (float*)d_out;

    cudaFuncSetAttribute(k_main, cudaFuncAttributeMaxDynamicSharedMemorySize,
                         SM_FLOATS * sizeof(float));
    k_main<<<GRID_MAIN, THREADS, SM_FLOATS * sizeof(float)>>>(
        x, bias, y, v0, v1, v2, scaling);
}

// round 11
// speedup vs baseline: 1.0697x; 1.0697x over previous
#include <cuda_runtime.h>

#define N 2048
#define K 16
#define BATCH 16384
#define RPB 16
#define THREADS 512
#define GRID_MAIN 152
#define NTILES (BATCH / RPB)
#define STAGES 8
#define INFLIGHT 6   // wait_group 6 -> 7 groups (3.5 KB) in flight per warp

// Final composed weights, layout [t][m4][rho][4]:
//   g_Wfin[((t*4 + (m>>2))*128 + rho)*4 + (m&3)]
__device__ float g_Wfin[K * K * 128];

// ---------------------------------------------------------------------------
// PDL primitives
// ---------------------------------------------------------------------------
__device__ __forceinline__ void pdl_launch_dependents() {
    asm volatile("griddepcontrol.launch_dependents;" ::: "memory");
}
__device__ __forceinline__ void pdl_wait() {
    asm volatile("griddepcontrol.wait;" ::: "memory");
}

// ---------------------------------------------------------------------------
// Fused precompute: Wfin = scaling * (W0 @ W1 @ W2).
// Composed pattern: c = (r + 128*s + 3) % N; r = rho + 128*t, m = (t+s)&15.
// First instruction releases the dependent launch of k_main (PDL): k_main's
// prologue (x prefetch) runs concurrently with this kernel.
// ---------------------------------------------------------------------------
__global__ void k_compose(const float* __restrict__ v0, const float* __restrict__ v1,
                          const float* __restrict__ v2, const float* __restrict__ scaling) {
    pdl_launch_dependents();

    __shared__ float w01[16][17];
    int s  = threadIdx.x & 15;
    int rl = threadIdx.x >> 4;
    int r  = blockIdx.x * 16 + rl;

    float acc = 0.f;
#pragma unroll
    for (int k0 = 0; k0 < K; k0++) {
        int arow = (r + 128 * k0) & (N - 1);
        acc = fmaf(v0[r * K + k0], v1[arow * K + ((s - k0) & (K - 1))], acc);
    }
    w01[rl][s] = acc;
    __syncthreads();

    float sc = scaling[0];
    float acc2 = 0.f;
#pragma unroll
    for (int s01 = 0; s01 < K; s01++) {
        int brow = (r + 128 * s01 + 1) & (N - 1);
        acc2 = fmaf(w01[rl][s01], v2[brow * K + ((s - s01) & (K - 1))], acc2);
    }
    int rho = r & 127;
    int t   = r >> 7;
    int m   = (t + s) & (K - 1);
    g_Wfin[((t * 4 + (m >> 2)) * 128 + rho) * 4 + (m & 3)] = sc * acc2;
}

// ---------------------------------------------------------------------------
// Packed f32x2 + cp.async helpers
// ---------------------------------------------------------------------------
__device__ __forceinline__ unsigned long long fma2(unsigned long long a,
                                                   unsigned long long b,
                                                   unsigned long long c) {
    unsigned long long d;
    asm("fma.rn.f32x2 %0, %1, %2, %3;" : "=l"(d) : "l"(a), "l"(b), "l"(c));
    return d;
}
__device__ __forceinline__ unsigned long long dup2(float v) {
    unsigned long long r;
    asm("mov.b64 %0, {%1, %1};" : "=l"(r) : "f"(v));
    return r;
}
__device__ __forceinline__ void unpack2(unsigned long long v, float& lo, float& hi) {
    asm("mov.b64 {%0, %1}, %2;" : "=f"(lo), "=f"(hi) : "l"(v));
}
__device__ __forceinline__ void cp_async16(unsigned smem_addr, const void* gptr) {
    asm volatile("cp.async.cg.shared.global [%0], [%1], 16;"
                 :: "r"(smem_addr), "l"(gptr) : "memory");
}
__device__ __forceinline__ void cp_commit() {
    asm volatile("cp.async.commit_group;" ::: "memory");
}
__device__ __forceinline__ void cp_wait() {
    asm volatile("cp.async.wait_group %0;" :: "n"(INFLIGHT) : "memory");
}

// ---------------------------------------------------------------------------
// Persistent main kernel: y = relu(x @ Wfin + bias).
//   y[row, (rho+3+128m)&2047] = sum_t x[row, rho+128t] * Wfin[t][m][rho]
//
// PDL: launched programmatically while k_compose runs. Issues the x cp.async
// prologue first (independent of Wfin), then griddepcontrol.wait, then loads
// W into smem. The compose kernel + launch gap are thus hidden behind the
// DRAM prefetch shadow.
//
// Main loop = validated R6 config: 16 warp-private 8-stage cp.async rings,
// no block barriers, W resident ([t][m4][rho][4] -> float4 IS two fma2
// operands), __stcs epilogue with warp-contiguous 128 B runs.
// ---------------------------------------------------------------------------
#define SM_W      0
#define SM_X      (32 * 1024)                       // floats
#define SM_BIAS   (SM_X + 16 * STAGES * 128)        // + 16384 = 49152
#define SM_FLOATS (SM_BIAS + N)                     // 51200 floats = 200 KB

__global__ void __launch_bounds__(THREADS, 1)
k_main(const float* __restrict__ x, const float* __restrict__ bias,
       float* __restrict__ y) {
    extern __shared__ float smem[];

    const int tid  = threadIdx.x;
    const int lane = tid & 31;
    const int warp = tid >> 5;
    const int grp  = warp >> 2;                 // 0..3 -> rows grp*4..grp*4+3
    const int wsub = warp & 3;                  // 32-rho window
    const int rho  = wsub * 32 + lane;
    const int crow = lane >> 3;                 // row this lane copies (0..3)
    const int coff = (lane & 7) * 4;            // float offset in 32-float window

    float* ring = smem + SM_X + warp * (STAGES * 128);
    const unsigned ring_sa = (unsigned)__cvta_generic_to_shared(ring)
                           + (unsigned)(crow * 32 + coff) * 4;
    const size_t lane_off = (size_t)(grp * 4 + crow) * N + wsub * 32 + coff;
    const size_t tile_step = (size_t)GRID_MAIN * RPB * N;

    int tile = blockIdx.x;
    const float* cur = x + (size_t)tile * RPB * N + lane_off;

    // Prologue FIRST (independent of Wfin): stages 0..6, 7 groups in flight.
    // This DRAM prefetch runs concurrently with k_compose under PDL.
#pragma unroll
    for (int s = 0; s < STAGES - 1; s++) {
        cp_async16(ring_sa + (unsigned)(s * 512), cur + s * 128);
        cp_commit();
    }

    // Wait for k_compose to fully complete (g_Wfin visible)
    pdl_wait();

    // Resident W (float4) + bias
    {
        const float4* src = (const float4*)g_Wfin;
        float4* dst = (float4*)(smem + SM_W);
#pragma unroll
        for (int i = tid; i < (K * K * 128) / 4; i += THREADS) dst[i] = src[i];
        for (int i = tid; i < N; i += THREADS) smem[SM_BIAS + i] = bias[i];
    }
    __syncthreads();

    for (; tile < NTILES; tile += GRID_MAIN) {
        const bool has_next = (tile + GRID_MAIN) < NTILES;
        const float* nxt = has_next ? cur + tile_step : cur;  // clamp: dummy re-read

        unsigned long long acc[4][8];
#pragma unroll
        for (int j = 0; j < 4; j++)
#pragma unroll
            for (int p = 0; p < 8; p++) acc[j][p] = 0ull;

#pragma unroll
        for (int t = 0; t < 16; t++) {
            cp_wait();
            __syncwarp();

            const float* xs = ring + (t & (STAGES - 1)) * 128;
            unsigned long long px0 = dup2(xs[lane]);
            unsigned long long px1 = dup2(xs[32 + lane]);
            unsigned long long px2 = dup2(xs[64 + lane]);
            unsigned long long px3 = dup2(xs[96 + lane]);

            // Refill: global stage t+7 (rolls into next tile at the tail)
            {
                const int s7 = t + (STAGES - 1);
                const float* src = (s7 < 16) ? (cur + s7 * 128)
                                             : (nxt + (s7 - 16) * 128);
                cp_async16(ring_sa + (unsigned)((s7 & (STAGES - 1)) * 512), src);
                cp_commit();
            }

            const float* wrow = smem + SM_W + t * 2048 + rho * 4;
#pragma unroll
            for (int m4 = 0; m4 < 4; m4++) {
                // float4 = two f32x2 operands for (m, m+1): no repacking
                ulonglong2 w = *(const ulonglong2*)(wrow + m4 * 512);
                acc[0][2 * m4]     = fma2(px0, w.x, acc[0][2 * m4]);
                acc[1][2 * m4]     = fma2(px1, w.x, acc[1][2 * m4]);
                acc[2][2 * m4]     = fma2(px2, w.x, acc[2][2 * m4]);
                acc[3][2 * m4]     = fma2(px3, w.x, acc[3][2 * m4]);
                acc[0][2 * m4 + 1] = fma2(px0, w.y, acc[0][2 * m4 + 1]);
                acc[1][2 * m4 + 1] = fma2(px1, w.y, acc[1][2 * m4 + 1]);
                acc[2][2 * m4 + 1] = fma2(px2, w.y, acc[2][2 * m4 + 1]);
                acc[3][2 * m4 + 1] = fma2(px3, w.y, acc[3][2 * m4 + 1]);
            }
        }
        cur = nxt;

        // Epilogue: bias + relu + streaming stores (warp-contiguous 128 B runs)
        float* yr = y + ((size_t)tile * RPB + grp * 4) * N;
#pragma unroll
        for (int p = 0; p < 8; p++) {
            const int c0 = (rho + 3 + 256 * p) & (N - 1);
            const int c1 = (c0 + 128) & (N - 1);
            const float b0 = smem[SM_BIAS + c0];
            const float b1 = smem[SM_BIAS + c1];
#pragma unroll
            for (int j = 0; j < 4; j++) {
                float lo, hi;
                unpack2(acc[j][p], lo, hi);
                __stcs(yr + (size_t)j * N + c0, fmaxf(lo + b0, 0.f));
                __stcs(yr + (size_t)j * N + c1, fmaxf(hi + b1, 0.f));
            }
        }
    }
}

// ---------------------------------------------------------------------------
// Launch: compose, then main with ProgrammaticStreamSerialization (PDL).
// Inputs: x, vals0, vals1, vals2, rows0, cols0, rows1, cols1, rows2, cols2,
//         scaling, bias
// ---------------------------------------------------------------------------
extern "C" void kernel_launch(void* const* d_in, const int* in_sizes, int n_in,
                              void* d_out, int out_size) {
    const float* x       = (const float*)d_in[0];
    const float* v0      = (const float*)d_in[1];
    const float* v1      = (const float*)d_in[2];
    const float* v2      = (const float*)d_in[3];
    const float* scaling = (const float*)d_in[10];
    const float* bias    = (const float*)d_in[11];
    float* y = (float*)d_out;

    k_compose<<<N / 16, 256>>>(v0, v1, v2, scaling);

    static int smem_set = 0;
    if (!smem_set) {
        cudaFuncSetAttribute(k_main, cudaFuncAttributeMaxDynamicSharedMemorySize,
                             SM_FLOATS * sizeof(float));
        smem_set = 1;
    }

    cudaLaunchConfig_t cfg = {};
    cfg.gridDim = dim3(GRID_MAIN, 1, 1);
    cfg.blockDim = dim3(THREADS, 1, 1);
    cfg.dynamicSmemBytes = SM_FLOATS * sizeof(float);
    cfg.stream = 0;
    cudaLaunchAttribute attr[1];
    attr[0].id = cudaLaunchAttributeProgrammaticStreamSerialization;
    attr[0].val.programmaticStreamSerializationAllowed = 1;
    cfg.attrs = attr;
    cfg.numAttrs = 1;
    cudaLaunchKernelEx(&cfg, k_main, x, bias, y);
}